// round 11
// baseline (speedup 1.0000x reference)
#include <cuda_runtime.h>

// CARAFE: features [2,64,64,256] f32, masks [2,128,128,25] f32, k=5, group=1.
// Nearest 64->128 half-pixel => src = dst >> 1.
// R11: LSU diet. Thread = 4 channels x 4 pixels (float4 everywhere):
//      LDS.128 200->100, LDG->40x.128, STG->16x.128 per thread, FFMA count
//      unchanged. Warps 0-1 cover pixels 0-3 (channels split 2x128), warps
//      2-3 cover pixels 4-7. Same d-major taps / rotating window / immediate
//      offsets / interior-border split as the 16.9us kernel.

#define FH 64
#define FW 64
#define C4 64      // 256 channels / 4 (float4 groups)
#define OH 128
#define OW 128
#define KK 25
#define SEGW 8
#define PXT 4      // pixels per thread

__device__ __forceinline__ void fma4(float4& a, const float4 f, const float m) {
    a.x = fmaf(f.x, m, a.x);
    a.y = fmaf(f.y, m, a.y);
    a.z = fmaf(f.z, m, a.z);
    a.w = fmaf(f.w, m, a.w);
}

template<bool CHK>
__device__ __forceinline__ void carafe_body(int seg, int hs, int b,
                                            const float4* __restrict__ F,
                                            float4* __restrict__ O,
                                            const float* __restrict__ smask,
                                            int c4g, int pxq)
{
    const int w0 = seg * SEGW + pxq;       // first pixel col for this warp pair
    const float4 z = make_float4(0.f, 0.f, 0.f, 0.f);

    // feature base at (row hs-2, col w0-2); all accesses immediate offsets.
    const float4* fb = F + ((b * FH + (hs - 2)) * FW + (w0 - 2)) * C4 + c4g;

    bool rok[5];
    #pragma unroll
    for (int r = 0; r < 5; r++) {
        int hr = hs - 2 + r;
        rok[r] = CHK ? (hr >= 0 && hr < FH) : true;
    }

    // 5-slot rotating float4 window: col (w0-2+j) -> slot j (mod 5)
    float4 w[5][5];
    #pragma unroll
    for (int j = 0; j < 5; j++) {
        bool cok = CHK ? ((w0 - 2 + j) >= 0 && (w0 - 2 + j) < FW) : true;
        #pragma unroll
        for (int r = 0; r < 5; r++)
            w[r][j] = (rok[r] && cok) ? fb[(r * FW + j) * C4] : z;
    }

    float4* ob = O + ((b * OH + 2 * hs) * OW + 2 * w0) * C4 + c4g;

    #pragma unroll
    for (int s = 0; s < PXT; s++) {
        // masks for pixel (pxq+s), source tap order p = r*5+d, float4 per tap
        const float4* __restrict__ mp =
            (const float4*)(smask + (pxq + s) * (KK * 4));

        float4 a0 = z, a1 = z, a2 = z, a3 = z;

        // d-major sweep; slot refilled at end of iter s-1 consumed only at d=4.
        #pragma unroll
        for (int d = 0; d < 5; d++) {
            #pragma unroll
            for (int r = 0; r < 5; r++) {
                const float4 f = w[r][(s + d) % 5];   // compile-time slot
                const float4 m = mp[r * 5 + d];       // broadcast LDS.128
                fma4(a0, f, m.x);
                fma4(a1, f, m.y);
                fma4(a2, f, m.z);
                fma4(a3, f, m.w);
            }
        }

        ob[(2 * s) * C4]          = a0;
        ob[(2 * s + 1) * C4]      = a1;
        ob[(OW + 2 * s) * C4]     = a2;
        ob[(OW + 2 * s + 1) * C4] = a3;

        if (s < PXT - 1) {
            // refill col (w0+s+3) into slot s%5; first consumed at iter s+1, d=4.
            const bool cok = CHK ? ((w0 + s + 3) < FW) : true;
            #pragma unroll
            for (int r = 0; r < 5; r++)
                w[r][s % 5] = (rok[r] && cok) ? fb[(r * FW + (s + 5)) * C4] : z;
        }
    }
}

__global__ __launch_bounds__(128, 3)
void carafe_kernel(const float* __restrict__ features,
                   const float* __restrict__ masks,
                   float* __restrict__ out)
{
    // smask layout: [px(8)][p(25)][out(4)], p = r*5+d (source order), out = oy*2+ox
    __shared__ __align__(16) float smask[SEGW * KK * 4];

    const int tid = threadIdx.x;
    const int seg = blockIdx.x;
    const int hs  = blockIdx.y;
    const int b   = blockIdx.z;
    const int ws0 = seg * SEGW;

    // ---- division-free mask transpose stage (R10) ----
    // tid = px*16 + o*4 + q; thread copies taps p = q+4k, immediate offsets.
    {
        const int q  = tid & 3;
        const int o  = (tid >> 2) & 3;
        const int px = tid >> 4;
        const int oy = o >> 1;
        const int ox = o & 1;

        const float* gm = masks
            + ((b * OH + 2 * hs + oy) * OW + 2 * (ws0 + px) + ox) * KK + q;
        float* sm = smask + px * (KK * 4) + q * 4 + o;

        #pragma unroll
        for (int k = 0; k < 7; k++) {
            if (k < 6 || q == 0)
                sm[k * 16] = gm[k * 4];
        }
    }
    __syncthreads();

    const float4* F = (const float4*)features;
    float4* O = (float4*)out;

    // warp mapping: w = tid>>5; channel half = w&1; pixel quad = (w>>1)*4
    const int lane = tid & 31;
    const int wrp  = tid >> 5;
    const int c4g  = (wrp & 1) * 32 + lane;   // float4 channel group 0..63
    const int pxq  = (wrp >> 1) * PXT;        // 0 or 4

    const bool interior = (seg >= 1) && (seg <= 6) && (hs >= 2) && (hs <= 61);
    if (interior)
        carafe_body<false>(seg, hs, b, F, O, smask, c4g, pxq);
    else
        carafe_body<true>(seg, hs, b, F, O, smask, c4g, pxq);
}

extern "C" void kernel_launch(void* const* d_in, const int* in_sizes, int n_in,
                              void* d_out, int out_size) {
    const float* features = (const float*)d_in[0];
    const float* masks    = (const float*)d_in[1];
    float* out            = (float*)d_out;

    dim3 grid(FW / SEGW, FH, 2);   // (8, 64, 2) = 1024 blocks x 4 warps
    carafe_kernel<<<grid, 128>>>(features, masks, out);
}